// round 8
// baseline (speedup 1.0000x reference)
#include <cuda_runtime.h>
#include <cstdint>

// ---------------------------------------------------------------------------
// SpinConvSq2dSparse: N=8, Lx=Ly=128, C=16, K=9 (-> 5 effective taps), F_IN=64
// Per-pixel GEMM I[4*64px, 48cols] = V @ W (K=80), fma.rn.f32x2 packed math.
// Round 8: 8 warps (256 thr), thread tile 8px x 6col (3 packed pairs).
// Crossbar law (measured R4/R6/R7): wf = lanes*bytes/128, no broadcast
// discount -> minimize (1/P + 1/Q) at fixed PQ*warps; keep 16 warps/SM.
// ---------------------------------------------------------------------------

#define TPAD 68      // feat tile row pad (floats); stride ≡ 4 mod 32 banks
#define NTP  194     // tile pixels: 66 (center+y halo) + 64 (x-1) + 64 (x+1)
#define WPAD 52      // weight row pad (floats)
#define IPAD 52      // intermediate row pad (floats); ≡ 20 mod 32 -> spread
#define TILE_FLOATS 13312                       // max(194*68=13192, 256*52=13312)
#define SMEM_FLOATS (2 * 80 * WPAD + TILE_FLOATS)   // 8320 + 13312 = 21632
#define SMEM_BYTES  (SMEM_FLOATS * 4)               // 86528 B

__device__ float g_WA[80 * WPAD];
__device__ float g_WB[80 * WPAD];

// ---- f32x2 helpers (sm_100a) ----
__device__ __forceinline__ unsigned long long f2dup(float x) {
    unsigned long long r;
    asm("mov.b64 %0, {%1, %1};" : "=l"(r) : "f"(x));
    return r;
}
__device__ __forceinline__ void fma2(unsigned long long& d,
                                     unsigned long long a,
                                     unsigned long long b) {
    asm("fma.rn.f32x2 %0, %1, %2, %0;" : "+l"(d) : "l"(a), "l"(b));
}
__device__ __forceinline__ void unpack2(unsigned long long v, float& lo, float& hi) {
    asm("mov.b64 {%0, %1}, %2;" : "=f"(lo), "=f"(hi) : "l"(v));
}

// ---------------------------------------------------------------------------
// Prep: build effective 5-tap weights with all scalar prefactors folded in.
// tap0 = sum of k=0..4 (all center); tap1..4 = k=5..8 -> (x-1),(x+1),(y-1),(y+1)
// cols: [0:16)=s110/a0-class, [16:32)=s101/b-class, [32:48)=t-class
// ---------------------------------------------------------------------------
__global__ void prep_weights(const float* __restrict__ w000,
                             const float* __restrict__ w011,
                             const float* __restrict__ w101,
                             const float* __restrict__ w110,
                             const float* __restrict__ w111) {
    int idx = blockIdx.x * blockDim.x + threadIdx.x;
    if (idx >= 80 * 48) return;
    int r   = idx / 48;        // (tap, c)
    int col = idx % 48;
    int tap = r / 16;
    int c   = r % 16;
    int cls = col / 16;
    int d   = col % 16;

    const double C0  = 0.28209479177387814;
    const double C1  = 0.4886025119029199;
    const double IS3 = 0.57735026918962576;   // 1/sqrt(3)
    const double IS6 = 0.40824829046386302;   // 1/sqrt(6)
    const double PW0 = 0.058925565098878960;  // sqrt(1/(9*2*16))
    const double PW1 = 1.0 / 12.0;            // sqrt(3/(9*3*16))

    int off = c * 16 + d;
    float s000, s011, s101, s110, s111;
    if (tap == 0) {
        s000 = s011 = s101 = s110 = s111 = 0.f;
        #pragma unroll
        for (int k = 0; k < 5; k++) {
            s000 += w000[k * 256 + off];
            s011 += w011[k * 256 + off];
            s101 += w101[k * 256 + off];
            s110 += w110[k * 256 + off];
            s111 += w111[k * 256 + off];
        }
    } else {
        int k = tap + 4;
        s000 = w000[k * 256 + off];
        s011 = w011[k * 256 + off];
        s101 = w101[k * 256 + off];
        s110 = w110[k * 256 + off];
        s111 = w111[k * 256 + off];
    }

    float a, b;
    if (cls == 0)      { a = (float)(PW0 * IS3 * C1) * s110;  b = (float)(PW0 * C0)       * s000; }
    else if (cls == 1) { a = (float)(PW1 * C0 * IS3) * s101;  b = (float)(PW1 * IS3 * C1) * s011; }
    else               { a = (float)(PW1 * IS6 * C1) * s111;  b = 0.f; }
    g_WA[r * WPAD + col] = a;
    g_WB[r * WPAD + col] = b;
}

// ---------------------------------------------------------------------------
// Main kernel: one CTA per (n, x, y-half of 64 pixels). 256 threads (8 warps).
// GEMM: 256 rows (4 g-groups x 64 px) x 48 cols, K=80.
// Warp w owns cols [6w, 6w+6); lane: g = lane>>3, p0 = lane&7, px = p0 + 8m.
// ---------------------------------------------------------------------------
__global__ __launch_bounds__(256, 2)
void spinconv_kernel(const float* __restrict__ feat,
                     const float* __restrict__ spin,
                     float* __restrict__ out) {
    extern __shared__ float smem[];
    float* sWA = smem;
    float* sWB = smem + 80 * WPAD;
    float* sT  = smem + 2 * 80 * WPAD;   // feat tile, later reused for intermediates

    const int b   = blockIdx.x;
    const int n   = b >> 8;
    const int x   = (b >> 1) & 127;
    const int y0  = (b & 1) << 6;
    const int tid = threadIdx.x;

    // ---- load weights into smem (vectorized) ----
    for (int i = tid; i < (80 * WPAD) / 4; i += 256) {
        ((float4*)sWA)[i] = ((const float4*)g_WA)[i];
        ((float4*)sWB)[i] = ((const float4*)g_WB)[i];
    }

    // ---- load feat tile (194 px x 64 floats), de-interleave to planes:
    //      [x0(16) | x1_i0(16) | x1_i1(16) | x1_i2(16)] per pixel row ----
    const int xm = (x + 127) & 127;
    const int xp = (x + 1) & 127;
    const size_t nbase = (size_t)n * (128 * 128 * 64);
    for (int idx = tid; idx < NTP * 16; idx += 256) {
        int tp = idx >> 4;
        int f4 = (idx & 15) << 2;
        int row, yy;
        if (tp < 66)       { row = x;  yy = (y0 + tp + 127) & 127; } // center row + y halo
        else if (tp < 130) { row = xm; yy = y0 + (tp - 66); }        // x-1
        else               { row = xp; yy = y0 + (tp - 130); }       // x+1
        float4 v = *(const float4*)(feat + nbase + ((size_t)row * 128 + yy) * 64 + f4);
        float vv[4] = {v.x, v.y, v.z, v.w};
        float* dst = sT + tp * TPAD;
        #pragma unroll
        for (int t = 0; t < 4; t++) {
            int f = f4 + t;
            int dpos;
            if (f < 16) dpos = f;
            else { int u = f - 16; dpos = (1 + (u % 3)) * 16 + (u / 3); }
            dst[dpos] = vv[t];
        }
    }
    __syncthreads();

    // ---- GEMM ----
    const int colg = tid >> 5;          // warp-uniform column group (0..7), 6 cols
    const int lane = tid & 31;
    const int g    = lane >> 3;         // 0..3 (uniform within each LDS phase)
    const int p0   = lane & 7;          // pixel base; thread does p0 + 8*m
    const int j0   = colg * 6;          // 24B offset -> 8B aligned
    const float* W     = (g == 3) ? sWB : sWA;
    const int    fbase = (g == 3) ? 0 : ((1 + g) << 4);   // plane start

    unsigned long long acc[8][3];
    #pragma unroll
    for (int m = 0; m < 8; m++) { acc[m][0] = 0ULL; acc[m][1] = 0ULL; acc[m][2] = 0ULL; }

    #pragma unroll
    for (int tap = 0; tap < 5; tap++) {
        // tile pixel index of tap for pixel p: center=1+p, x-1=66+p, x+1=130+p, y-1=p, y+1=2+p
        const int base = (tap == 0) ? 1 : (tap == 1) ? 66 : (tap == 2) ? 130 : (tap == 3) ? 0 : 2;
        const float* tb = sT + (base + p0) * TPAD + fbase;
        const float* wr = W + tap * (16 * WPAD) + j0;
        #pragma unroll
        for (int c4 = 0; c4 < 4; c4++) {
            // hoist weights: 4 k-values x 3 col-pairs (8B-aligned LDS.64)
            unsigned long long wp[4][3];
            #pragma unroll
            for (int cc = 0; cc < 4; cc++) {
                wp[cc][0] = *(const unsigned long long*)(wr + cc * WPAD + 0);
                wp[cc][1] = *(const unsigned long long*)(wr + cc * WPAD + 2);
                wp[cc][2] = *(const unsigned long long*)(wr + cc * WPAD + 4);
            }
            wr += 4 * WPAD;
            #pragma unroll
            for (int m = 0; m < 8; m++) {
                float4 v = *(const float4*)(tb + 8 * m * TPAD);
                const float xs[4] = {v.x, v.y, v.z, v.w};
                #pragma unroll
                for (int cc = 0; cc < 4; cc++) {
                    unsigned long long xd = f2dup(xs[cc]);
                    fma2(acc[m][0], xd, wp[cc][0]);
                    fma2(acc[m][1], xd, wp[cc][1]);
                    fma2(acc[m][2], xd, wp[cc][2]);
                }
            }
            tb += 4;
        }
    }
    __syncthreads();   // tile no longer needed; reuse sT for intermediates

    // ---- stash intermediates I[row=g*64+p][48] (pad IPAD) ----
    #pragma unroll
    for (int m = 0; m < 8; m++) {
        float o[6];
        unpack2(acc[m][0], o[0], o[1]);
        unpack2(acc[m][1], o[2], o[3]);
        unpack2(acc[m][2], o[4], o[5]);
        float* dst = sT + ((g << 6) + p0 + 8 * m) * IPAD + j0;
        *(float2*)(dst + 0) = make_float2(o[0], o[1]);
        *(float2*)(dst + 2) = make_float2(o[2], o[3]);
        *(float2*)(dst + 4) = make_float2(o[4], o[5]);
    }
    __syncthreads();

    // ---- epilogue: 4 threads per pixel, each does 4 d's ----
    {
        const int p  = tid >> 2;
        const int d0 = (tid & 3) << 2;
        const size_t q = ((size_t)n * 128 + x) * 128 + (y0 + p);
        const float s0 = spin[q * 3 + 1];
        const float s1 = spin[q * 3 + 2];
        const float s2 = spin[q * 3 + 0];

        const float* I0 = sT + (0 * 64 + p) * IPAD;    // i=0 block
        const float* I1 = sT + (1 * 64 + p) * IPAD;    // i=1
        const float* I2 = sT + (2 * 64 + p) * IPAD;    // i=2
        const float* I3 = sT + (3 * 64 + p) * IPAD;    // x0 block: [a0|b|-]

        float o0[4], o1[12];
        #pragma unroll
        for (int t = 0; t < 4; t++) {
            const int d = d0 + t;
            const float a0 = I3[d];
            const float bv = I3[16 + d];
            const float h0 = I0[d],      h1 = I1[d],      h2 = I2[d];       // s110
            const float a1 = I0[16 + d], b1 = I1[16 + d], c1 = I2[16 + d];  // s101
            const float t0 = I0[32 + d], t1 = I1[32 + d], t2 = I2[32 + d];  // t

            o0[t] = a0 + h0 * s0 + h1 * s1 + h2 * s2;
            const float cx = t1 * s2 - t2 * s1;
            const float cy = t2 * s0 - t0 * s2;
            const float cz = t0 * s1 - t1 * s0;
            o1[t * 3 + 0] = fmaf(bv, s0, a1) + cx;
            o1[t * 3 + 1] = fmaf(bv, s1, b1) + cy;
            o1[t * 3 + 2] = fmaf(bv, s2, c1) + cz;
        }

        float* op = out + q * 64;
        *(float4*)(op + d0) = make_float4(o0[0], o0[1], o0[2], o0[3]);
        const int ob = 16 + 3 * d0;
        *(float4*)(op + ob + 0) = make_float4(o1[0], o1[1], o1[2],  o1[3]);
        *(float4*)(op + ob + 4) = make_float4(o1[4], o1[5], o1[6],  o1[7]);
        *(float4*)(op + ob + 8) = make_float4(o1[8], o1[9], o1[10], o1[11]);
    }
}

// ---------------------------------------------------------------------------
extern "C" void kernel_launch(void* const* d_in, const int* in_sizes, int n_in,
                              void* d_out, int out_size) {
    const float* feat = (const float*)d_in[0];
    const float* spin = (const float*)d_in[1];
    const float* w000 = (const float*)d_in[2];
    const float* w011 = (const float*)d_in[3];
    const float* w101 = (const float*)d_in[4];
    const float* w110 = (const float*)d_in[5];
    const float* w111 = (const float*)d_in[6];
    float* out = (float*)d_out;

    (void)in_sizes; (void)n_in; (void)out_size;

    cudaFuncSetAttribute(spinconv_kernel,
                         cudaFuncAttributeMaxDynamicSharedMemorySize, SMEM_BYTES);

    prep_weights<<<(80 * 48 + 255) / 256, 256>>>(w000, w011, w101, w110, w111);
    spinconv_kernel<<<8 * 128 * 2, 256, SMEM_BYTES>>>(feat, spin, out);
}

// round 9
// speedup vs baseline: 1.8076x; 1.8076x over previous
#include <cuda_runtime.h>
#include <cstdint>

// ---------------------------------------------------------------------------
// SpinConvSq2dSparse: N=8, Lx=Ly=128, C=16, K=9 (-> 5 effective taps), F_IN=64
// Round 9: tf32 mma.sync.m16n8k8 tensor cores.
// Per-CTA GEMM I[256 rows, 48 cols] = V @ W, K=80 (5 taps x 16 ch):
//   16 m-tiles (16 rows) x 6 n-tiles (8 cols) x 10 k-steps (8).
//   8 warps, each owns 2 m-tiles x 6 n-tiles (12 accs).
//   A fragments via ldmatrix.x4 from the de-interleaved pixel-major tile;
//   B fragments via scalar LDS from tf32-rounded weights (WPAD=56: the
//   (k%4)*56 + n/4 lane pattern covers all 32 banks, conflict-free).
// Epilogue (spin contraction + cross product) unchanged, fp32.
// ---------------------------------------------------------------------------

#define TPAD 68      // feat tile row pad (floats); 16B rows, ldmatrix conflict-free
#define NTP  194     // tile pixels: 66 (center+y halo) + 64 (x-1) + 64 (x+1)
#define WPAD 56      // weight row pad; B-fragment LDS bank-conflict-free
#define IPAD 52      // intermediate row pad (floats)
#define TILE_FLOATS 13312                       // max(194*68=13192, 256*52=13312)
#define SMEM_FLOATS (2 * 80 * WPAD + TILE_FLOATS)   // 8960 + 13312 = 22272
#define SMEM_BYTES  (SMEM_FLOATS * 4)               // 89088 B

__device__ float g_WA[80 * WPAD];
__device__ float g_WB[80 * WPAD];

// ---- tf32 / mma helpers (sm_100a) ----
__device__ __forceinline__ float to_tf32(float x) {
    uint32_t u;
    asm("cvt.rna.tf32.f32 %0, %1;" : "=r"(u) : "f"(x));
    return __uint_as_float(u);
}
__device__ __forceinline__ void ldsm_x4(uint32_t* r, uint32_t addr) {
    asm volatile("ldmatrix.sync.aligned.m8n8.x4.shared.b16 {%0,%1,%2,%3}, [%4];"
                 : "=r"(r[0]), "=r"(r[1]), "=r"(r[2]), "=r"(r[3]) : "r"(addr));
}
__device__ __forceinline__ void mma_tf32(float* c, const uint32_t* a, const uint32_t* b) {
    asm volatile("mma.sync.aligned.m16n8k8.row.col.f32.tf32.tf32.f32 "
                 "{%0,%1,%2,%3}, {%4,%5,%6,%7}, {%8,%9}, {%0,%1,%2,%3};"
                 : "+f"(c[0]), "+f"(c[1]), "+f"(c[2]), "+f"(c[3])
                 : "r"(a[0]), "r"(a[1]), "r"(a[2]), "r"(a[3]),
                   "r"(b[0]), "r"(b[1]));
}

// ---------------------------------------------------------------------------
// Prep: build effective 5-tap weights (prefactors folded), tf32-rounded.
// tap0 = sum of k=0..4 (center); tap1..4 = k=5..8 -> (x-1),(x+1),(y-1),(y+1)
// cols: [0:16)=s110/a0-class, [16:32)=s101/b-class, [32:48)=t-class
// ---------------------------------------------------------------------------
__global__ void prep_weights(const float* __restrict__ w000,
                             const float* __restrict__ w011,
                             const float* __restrict__ w101,
                             const float* __restrict__ w110,
                             const float* __restrict__ w111) {
    int idx = blockIdx.x * blockDim.x + threadIdx.x;
    if (idx >= 80 * 48) return;
    int r   = idx / 48;        // (tap, c)
    int col = idx % 48;
    int tap = r / 16;
    int c   = r % 16;
    int cls = col / 16;
    int d   = col % 16;

    const double C0  = 0.28209479177387814;
    const double C1  = 0.4886025119029199;
    const double IS3 = 0.57735026918962576;   // 1/sqrt(3)
    const double IS6 = 0.40824829046386302;   // 1/sqrt(6)
    const double PW0 = 0.058925565098878960;  // sqrt(1/(9*2*16))
    const double PW1 = 1.0 / 12.0;            // sqrt(3/(9*3*16))

    int off = c * 16 + d;
    float s000, s011, s101, s110, s111;
    if (tap == 0) {
        s000 = s011 = s101 = s110 = s111 = 0.f;
        #pragma unroll
        for (int k = 0; k < 5; k++) {
            s000 += w000[k * 256 + off];
            s011 += w011[k * 256 + off];
            s101 += w101[k * 256 + off];
            s110 += w110[k * 256 + off];
            s111 += w111[k * 256 + off];
        }
    } else {
        int k = tap + 4;
        s000 = w000[k * 256 + off];
        s011 = w011[k * 256 + off];
        s101 = w101[k * 256 + off];
        s110 = w110[k * 256 + off];
        s111 = w111[k * 256 + off];
    }

    float a, b;
    if (cls == 0)      { a = (float)(PW0 * IS3 * C1) * s110;  b = (float)(PW0 * C0)       * s000; }
    else if (cls == 1) { a = (float)(PW1 * C0 * IS3) * s101;  b = (float)(PW1 * IS3 * C1) * s011; }
    else               { a = (float)(PW1 * IS6 * C1) * s111;  b = 0.f; }
    g_WA[r * WPAD + col] = to_tf32(a);
    g_WB[r * WPAD + col] = to_tf32(b);
}

// ---------------------------------------------------------------------------
// Main kernel: one CTA per (n, x, y-half of 64 pixels). 256 threads (8 warps).
// ---------------------------------------------------------------------------
__global__ __launch_bounds__(256, 2)
void spinconv_kernel(const float* __restrict__ feat,
                     const float* __restrict__ spin,
                     float* __restrict__ out) {
    extern __shared__ float smem[];
    float* sWA = smem;
    float* sWB = smem + 80 * WPAD;
    float* sT  = smem + 2 * 80 * WPAD;   // feat tile, later reused for intermediates

    const int b   = blockIdx.x;
    const int n   = b >> 8;
    const int x   = (b >> 1) & 127;
    const int y0  = (b & 1) << 6;
    const int tid = threadIdx.x;

    // ---- load weights into smem (vectorized) ----
    for (int i = tid; i < (80 * WPAD) / 4; i += 256) {
        ((float4*)sWA)[i] = ((const float4*)g_WA)[i];
        ((float4*)sWB)[i] = ((const float4*)g_WB)[i];
    }

    // ---- load feat tile (194 px x 64 floats), de-interleave to planes:
    //      [x0(16) | x1_i0(16) | x1_i1(16) | x1_i2(16)], tf32-rounded ----
    const int xm = (x + 127) & 127;
    const int xp = (x + 1) & 127;
    const size_t nbase = (size_t)n * (128 * 128 * 64);
    for (int idx = tid; idx < NTP * 16; idx += 256) {
        int tp = idx >> 4;
        int f4 = (idx & 15) << 2;
        int row, yy;
        if (tp < 66)       { row = x;  yy = (y0 + tp + 127) & 127; } // center row + y halo
        else if (tp < 130) { row = xm; yy = y0 + (tp - 66); }        // x-1
        else               { row = xp; yy = y0 + (tp - 130); }       // x+1
        float4 v = *(const float4*)(feat + nbase + ((size_t)row * 128 + yy) * 64 + f4);
        float vv[4] = {to_tf32(v.x), to_tf32(v.y), to_tf32(v.z), to_tf32(v.w)};
        float* dst = sT + tp * TPAD;
        #pragma unroll
        for (int t = 0; t < 4; t++) {
            int f = f4 + t;
            int dpos;
            if (f < 16) dpos = f;
            else { int u = f - 16; dpos = (1 + (u % 3)) * 16 + (u / 3); }
            dst[dpos] = vv[t];
        }
    }
    __syncthreads();

    // ---- tensor-core GEMM ----
    const int w    = tid >> 5;          // warp 0..7; m-tiles 2w, 2w+1
    const int lane = tid & 31;
    const int g    = (2 * w) >> 2;      // 0..3 (warp-uniform)
    const int P0a  = ((2 * w) & 3) << 4;   // pixel base of first m-tile (0 or 32)
    const float* W     = (g == 3) ? sWB : sWA;
    const int    fbase = (g == 3) ? 0 : ((1 + g) << 4);

    const int laneRow = lane & 15;           // A fragment row within m-tile
    const int colOff  = (lane & 16) ? 4 : 0; // A fragment k sub-offset
    const uint32_t sT32 = (uint32_t)__cvta_generic_to_shared(sT);

    float acc[2][6][4];
    #pragma unroll
    for (int mt = 0; mt < 2; mt++)
        #pragma unroll
        for (int nt = 0; nt < 6; nt++)
            #pragma unroll
            for (int i = 0; i < 4; i++) acc[mt][nt][i] = 0.f;

    #pragma unroll
    for (int tap = 0; tap < 5; tap++) {
        // tile pixel of tap for pixel p: center=1+p, x-1=66+p, x+1=130+p, y-1=p, y+1=2+p
        const int tapbase = (tap == 0) ? 1 : (tap == 1) ? 66 : (tap == 2) ? 130 : (tap == 3) ? 0 : 2;
        #pragma unroll
        for (int k0 = 0; k0 < 16; k0 += 8) {
            // A fragments for both m-tiles (ldmatrix x4, conflict-free)
            uint32_t a[2][4];
            #pragma unroll
            for (int mt = 0; mt < 2; mt++) {
                int row = tapbase + P0a + 16 * mt + laneRow;
                uint32_t addr = sT32 + 4u * (uint32_t)(row * TPAD + fbase + k0 + colOff);
                ldsm_x4(a[mt], addr);
            }
            // B fragments: 6 n-tiles (scalar LDS, bank-spread by WPAD=56)
            const float* wk = W + (tap * 16 + k0 + (lane & 3)) * WPAD + (lane >> 2);
            uint32_t bf[6][2];
            #pragma unroll
            for (int nt = 0; nt < 6; nt++) {
                bf[nt][0] = __float_as_uint(wk[8 * nt]);
                bf[nt][1] = __float_as_uint(wk[8 * nt + 4 * WPAD]);
            }
            #pragma unroll
            for (int mt = 0; mt < 2; mt++)
                #pragma unroll
                for (int nt = 0; nt < 6; nt++)
                    mma_tf32(acc[mt][nt], a[mt], bf[nt]);
        }
    }
    __syncthreads();   // tile no longer needed; reuse sT for intermediates

    // ---- stash intermediates I[row=g*64+p][48] (pad IPAD) ----
    // D fragment: c0,c1 at (row lane/4, col 2(lane%4)+{0,1}); c2,c3 at row+8.
    #pragma unroll
    for (int mt = 0; mt < 2; mt++) {
        const int rbase = (g << 6) + P0a + 16 * mt + (lane >> 2);
        #pragma unroll
        for (int nt = 0; nt < 6; nt++) {
            const int cbase = 8 * nt + 2 * (lane & 3);
            *(float2*)(sT + rbase * IPAD + cbase)       = make_float2(acc[mt][nt][0], acc[mt][nt][1]);
            *(float2*)(sT + (rbase + 8) * IPAD + cbase) = make_float2(acc[mt][nt][2], acc[mt][nt][3]);
        }
    }
    __syncthreads();

    // ---- epilogue: 4 threads per pixel, each does 4 d's (fp32) ----
    {
        const int p  = tid >> 2;
        const int d0 = (tid & 3) << 2;
        const size_t q = ((size_t)n * 128 + x) * 128 + (y0 + p);
        const float s0 = spin[q * 3 + 1];
        const float s1 = spin[q * 3 + 2];
        const float s2 = spin[q * 3 + 0];

        const float* I0 = sT + (0 * 64 + p) * IPAD;    // i=0 block
        const float* I1 = sT + (1 * 64 + p) * IPAD;    // i=1
        const float* I2 = sT + (2 * 64 + p) * IPAD;    // i=2
        const float* I3 = sT + (3 * 64 + p) * IPAD;    // x0 block: [a0|b|-]

        float o0[4], o1[12];
        #pragma unroll
        for (int t = 0; t < 4; t++) {
            const int d = d0 + t;
            const float a0 = I3[d];
            const float bv = I3[16 + d];
            const float h0 = I0[d],      h1 = I1[d],      h2 = I2[d];       // s110
            const float a1 = I0[16 + d], b1 = I1[16 + d], c1 = I2[16 + d];  // s101
            const float t0 = I0[32 + d], t1 = I1[32 + d], t2 = I2[32 + d];  // t

            o0[t] = a0 + h0 * s0 + h1 * s1 + h2 * s2;
            const float cx = t1 * s2 - t2 * s1;
            const float cy = t2 * s0 - t0 * s2;
            const float cz = t0 * s1 - t1 * s0;
            o1[t * 3 + 0] = fmaf(bv, s0, a1) + cx;
            o1[t * 3 + 1] = fmaf(bv, s1, b1) + cy;
            o1[t * 3 + 2] = fmaf(bv, s2, c1) + cz;
        }

        float* op = out + q * 64;
        *(float4*)(op + d0) = make_float4(o0[0], o0[1], o0[2], o0[3]);
        const int ob = 16 + 3 * d0;
        *(float4*)(op + ob + 0) = make_float4(o1[0], o1[1], o1[2],  o1[3]);
        *(float4*)(op + ob + 4) = make_float4(o1[4], o1[5], o1[6],  o1[7]);
        *(float4*)(op + ob + 8) = make_float4(o1[8], o1[9], o1[10], o1[11]);
    }
}

// ---------------------------------------------------------------------------
extern "C" void kernel_launch(void* const* d_in, const int* in_sizes, int n_in,
                              void* d_out, int out_size) {
    const float* feat = (const float*)d_in[0];
    const float* spin = (const float*)d_in[1];
    const float* w000 = (const float*)d_in[2];
    const float* w011 = (const float*)d_in[3];
    const float* w101 = (const float*)d_in[4];
    const float* w110 = (const float*)d_in[5];
    const float* w111 = (const float*)d_in[6];
    float* out = (float*)d_out;

    (void)in_sizes; (void)n_in; (void)out_size;

    cudaFuncSetAttribute(spinconv_kernel,
                         cudaFuncAttributeMaxDynamicSharedMemorySize, SMEM_BYTES);

    prep_weights<<<(80 * 48 + 255) / 256, 256>>>(w000, w011, w101, w110, w111);
    spinconv_kernel<<<8 * 128 * 2, 256, SMEM_BYTES>>>(feat, spin, out);
}

// round 10
// speedup vs baseline: 2.2370x; 1.2376x over previous
#include <cuda_runtime.h>
#include <cuda_fp16.h>
#include <cstdint>

// ---------------------------------------------------------------------------
// SpinConvSq2dSparse: N=8, Lx=Ly=128, C=16, K=9 (-> 5 effective taps), F_IN=64
// Round 10: f16 mma.sync.m16n8k16 (same 10-bit mantissa as tf32 -> same err).
//   - one k16 MMA step per tap (K=80 -> 5 steps)
//   - B fragments pre-swizzled by prep kernel into per-lane u32 words:
//     unit-stride conflict-free LDS.32, no address math
//   - f16 tile (halved LDSM traffic), smem 63KB -> 3 CTAs/SM (24 warps)
//   - IPAD=48: conflict-free stash + float4-vectorized epilogue loads
// ---------------------------------------------------------------------------

#define TPH  72      // f16 per tile pixel row (144B, ldmatrix conflict-free)
#define NTP  194     // tile pixels: 66 (center+y halo) + 64 (x-1) + 64 (x+1)
#define IPAD 48      // intermediate row pad (floats); ≡16 mod 32
#define NWFRAG 3840  // 2 arrays x 5 taps x 6 nt x 2 regs x 32 lanes (u32)
#define TILE_FLOATS 12288                    // max(194*72/2=6984, 256*48=12288)
#define SMEM_FLOATS (NWFRAG + TILE_FLOATS)   // 16128 floats
#define SMEM_BYTES  (SMEM_FLOATS * 4)        // 64512 B -> 3 CTAs/SM

__device__ uint32_t g_Bfrag[NWFRAG];

// ---- mma helpers (sm_100a) ----
__device__ __forceinline__ void ldsm_x4(uint32_t* r, uint32_t addr) {
    asm volatile("ldmatrix.sync.aligned.m8n8.x4.shared.b16 {%0,%1,%2,%3}, [%4];"
                 : "=r"(r[0]), "=r"(r[1]), "=r"(r[2]), "=r"(r[3]) : "r"(addr));
}
__device__ __forceinline__ void mma_f16(float* c, const uint32_t* a, const uint32_t* b) {
    asm volatile("mma.sync.aligned.m16n8k16.row.col.f32.f16.f16.f32 "
                 "{%0,%1,%2,%3}, {%4,%5,%6,%7}, {%8,%9}, {%0,%1,%2,%3};"
                 : "+f"(c[0]), "+f"(c[1]), "+f"(c[2]), "+f"(c[3])
                 : "r"(a[0]), "r"(a[1]), "r"(a[2]), "r"(a[3]),
                   "r"(b[0]), "r"(b[1]));
}

// ---------------------------------------------------------------------------
// Effective weight (prefactors folded). tap0 = sum k=0..4 (center);
// tap1..4 = k=5..8 -> (x-1),(x+1),(y-1),(y+1).
// cols n: [0:16)=s110/a0-class, [16:32)=s101/b-class, [32:48)=t-class
// ---------------------------------------------------------------------------
__device__ __forceinline__ float effw(int isB, int tap, int c, int n,
                                      const float* w000, const float* w011,
                                      const float* w101, const float* w110,
                                      const float* w111) {
    const double C0  = 0.28209479177387814;
    const double C1  = 0.4886025119029199;
    const double IS3 = 0.57735026918962576;
    const double IS6 = 0.40824829046386302;
    const double PW0 = 0.058925565098878960;   // sqrt(1/(9*2*16))
    const double PW1 = 1.0 / 12.0;             // sqrt(3/(9*3*16))
    int cls = n >> 4, d = n & 15;
    int off = c * 16 + d;
    const float* w;
    double pf;
    if (!isB) {
        if (cls == 0)      { w = w110; pf = PW0 * IS3 * C1; }
        else if (cls == 1) { w = w101; pf = PW1 * C0 * IS3; }
        else               { w = w111; pf = PW1 * IS6 * C1; }
    } else {
        if (cls == 0)      { w = w000; pf = PW0 * C0; }
        else if (cls == 1) { w = w011; pf = PW1 * IS3 * C1; }
        else               return 0.f;
    }
    float s;
    if (tap == 0) {
        s = 0.f;
        #pragma unroll
        for (int k = 0; k < 5; k++) s += w[k * 256 + off];
    } else {
        s = w[(tap + 4) * 256 + off];
    }
    return (float)(pf * (double)s);
}

// Prep: emit B fragments in HMMA per-lane layout, packed f16x2.
// idx = arr*1920 + tap*384 + nt*64 + r*32 + lane
// fragment reg r: k-pair = 2*(lane&3) + 8r (+1); col n = 8*nt + lane/4.
__global__ void prep_weights(const float* __restrict__ w000,
                             const float* __restrict__ w011,
                             const float* __restrict__ w101,
                             const float* __restrict__ w110,
                             const float* __restrict__ w111) {
    int idx = blockIdx.x * blockDim.x + threadIdx.x;
    if (idx >= NWFRAG) return;
    int l   = idx & 31;
    int r   = (idx >> 5) & 1;
    int nt  = (idx >> 6) % 6;
    int tap = ((idx >> 6) / 6) % 5;
    int arr = idx / 1920;
    int n  = 8 * nt + (l >> 2);
    int c0 = 2 * (l & 3) + 8 * r;
    float v0 = effw(arr, tap, c0,     n, w000, w011, w101, w110, w111);
    float v1 = effw(arr, tap, c0 + 1, n, w000, w011, w101, w110, w111);
    __half2 h = __floats2half2_rn(v0, v1);
    g_Bfrag[idx] = *(uint32_t*)&h;
}

// ---------------------------------------------------------------------------
// Main kernel: one CTA per (n, x, y-half of 64 pixels). 256 threads (8 warps).
// GEMM: 256 rows (4 g-groups x 64 px) x 48 cols, K=80 = 5 taps x k16.
// Warp w: m-tiles 2w,2w+1 (g = w>>1, pixel base (w&1)*32), all 6 n-tiles.
// ---------------------------------------------------------------------------
__global__ __launch_bounds__(256, 3)
void spinconv_kernel(const float* __restrict__ feat,
                     const float* __restrict__ spin,
                     float* __restrict__ out) {
    extern __shared__ float smem[];
    uint32_t* sBw  = (uint32_t*)smem;          // 3840 u32 fragment words
    float*    sT   = smem + NWFRAG;            // tile (f16) then intermediates (f32)
    __half*   tileH = (__half*)sT;

    const int b   = blockIdx.x;
    const int n   = b >> 8;
    const int x   = (b >> 1) & 127;
    const int y0  = (b & 1) << 6;
    const int tid = threadIdx.x;

    // ---- copy pre-swizzled weight fragments to smem ----
    {
        const uint4* src = (const uint4*)g_Bfrag;
        uint4* dst = (uint4*)sBw;
        for (int i = tid; i < NWFRAG / 4; i += 256) dst[i] = src[i];
    }

    // ---- load feat tile (194 px x 64), de-interleave to f16 planes:
    //      [x0(16) | x1_i0(16) | x1_i1(16) | x1_i2(16)] per pixel row ----
    const int xm = (x + 127) & 127;
    const int xp = (x + 1) & 127;
    const size_t nbase = (size_t)n * (128 * 128 * 64);
    for (int idx = tid; idx < NTP * 16; idx += 256) {
        int tp = idx >> 4;
        int f4 = (idx & 15) << 2;
        int row, yy;
        if (tp < 66)       { row = x;  yy = (y0 + tp + 127) & 127; } // center + y halo
        else if (tp < 130) { row = xm; yy = y0 + (tp - 66); }        // x-1
        else               { row = xp; yy = y0 + (tp - 130); }       // x+1
        float4 v = *(const float4*)(feat + nbase + ((size_t)row * 128 + yy) * 64 + f4);
        __half* dst = tileH + tp * TPH;
        if (f4 < 16) {
            *(__half2*)(dst + f4)     = __floats2half2_rn(v.x, v.y);
            *(__half2*)(dst + f4 + 2) = __floats2half2_rn(v.z, v.w);
        } else {
            float vv[4] = {v.x, v.y, v.z, v.w};
            #pragma unroll
            for (int t = 0; t < 4; t++) {
                int u = f4 - 16 + t;
                int dpos = (1 + (u % 3)) * 16 + u / 3;
                dst[dpos] = __float2half_rn(vv[t]);
            }
        }
    }
    __syncthreads();

    // ---- tensor-core GEMM (f16 inputs, f32 accum) ----
    const int w    = tid >> 5;
    const int lane = tid & 31;
    const int g    = w >> 1;                  // 0..3 (warp-uniform)
    const int P0a  = (w & 1) << 5;            // pixel base of first m-tile
    const uint32_t* sB = sBw + ((g == 3) ? 1920 : 0);
    const int fb2  = ((g == 3) ? 0 : ((1 + g) << 4)) * 2;  // plane byte offset
    const int laneRow = lane & 15;
    const int cOffB   = (lane & 16) ? 16 : 0;              // k-half byte offset
    const uint32_t tbase = (uint32_t)__cvta_generic_to_shared(tileH);

    float acc[2][6][4];
    #pragma unroll
    for (int mt = 0; mt < 2; mt++)
        #pragma unroll
        for (int nt = 0; nt < 6; nt++)
            #pragma unroll
            for (int i = 0; i < 4; i++) acc[mt][nt][i] = 0.f;

    #pragma unroll
    for (int tap = 0; tap < 5; tap++) {
        // tile pixel of tap for pixel p: center=1+p, x-1=66+p, x+1=130+p, y-1=p, y+1=2+p
        const int tapbase = (tap == 0) ? 1 : (tap == 1) ? 66 : (tap == 2) ? 130 : (tap == 3) ? 0 : 2;
        uint32_t a[2][4];
        #pragma unroll
        for (int mt = 0; mt < 2; mt++) {
            int row = tapbase + P0a + 16 * mt + laneRow;
            ldsm_x4(a[mt], tbase + (uint32_t)(row * (TPH * 2) + fb2 + cOffB));
        }
        const uint32_t* bp = sB + tap * 384 + lane;
        uint32_t bf[6][2];
        #pragma unroll
        for (int nt = 0; nt < 6; nt++) {
            bf[nt][0] = bp[nt * 64];
            bf[nt][1] = bp[nt * 64 + 32];
        }
        #pragma unroll
        for (int mt = 0; mt < 2; mt++)
            #pragma unroll
            for (int nt = 0; nt < 6; nt++)
                mma_f16(acc[mt][nt], a[mt], bf[nt]);
    }
    __syncthreads();   // tile no longer needed; reuse sT for intermediates

    // ---- stash intermediates I[row=g*64+p][48] (pad IPAD=48) ----
    // D fragment: c0,c1 at (row lane/4, col 2(lane%4)+{0,1}); c2,c3 at row+8.
    #pragma unroll
    for (int mt = 0; mt < 2; mt++) {
        const int rbase = (g << 6) + P0a + 16 * mt + (lane >> 2);
        #pragma unroll
        for (int nt = 0; nt < 6; nt++) {
            const int cb = 8 * nt + 2 * (lane & 3);
            *(float2*)(sT + rbase * IPAD + cb)       = make_float2(acc[mt][nt][0], acc[mt][nt][1]);
            *(float2*)(sT + (rbase + 8) * IPAD + cb) = make_float2(acc[mt][nt][2], acc[mt][nt][3]);
        }
    }
    __syncthreads();

    // ---- epilogue: 4 threads per pixel, each does 4 d's (fp32, float4 LDS) ----
    {
        const int p  = tid >> 2;
        const int d0 = (tid & 3) << 2;
        const size_t q = ((size_t)n * 128 + x) * 128 + (y0 + p);
        const float s0 = spin[q * 3 + 1];
        const float s1 = spin[q * 3 + 2];
        const float s2 = spin[q * 3 + 0];

        const float* I0 = sT + (0 * 64 + p) * IPAD;
        const float* I1 = sT + (1 * 64 + p) * IPAD;
        const float* I2 = sT + (2 * 64 + p) * IPAD;
        const float* I3 = sT + (3 * 64 + p) * IPAD;

        float A0[4], BV[4], H[3][4], A1[3][4], T[3][4];
        *(float4*)A0 = *(const float4*)(I3 + d0);
        *(float4*)BV = *(const float4*)(I3 + 16 + d0);
        *(float4*)H[0]  = *(const float4*)(I0 + d0);
        *(float4*)H[1]  = *(const float4*)(I1 + d0);
        *(float4*)H[2]  = *(const float4*)(I2 + d0);
        *(float4*)A1[0] = *(const float4*)(I0 + 16 + d0);
        *(float4*)A1[1] = *(const float4*)(I1 + 16 + d0);
        *(float4*)A1[2] = *(const float4*)(I2 + 16 + d0);
        *(float4*)T[0]  = *(const float4*)(I0 + 32 + d0);
        *(float4*)T[1]  = *(const float4*)(I1 + 32 + d0);
        *(float4*)T[2]  = *(const float4*)(I2 + 32 + d0);

        float o0[4], o1[12];
        #pragma unroll
        for (int t = 0; t < 4; t++) {
            o0[t] = A0[t] + H[0][t] * s0 + H[1][t] * s1 + H[2][t] * s2;
            const float cx = T[1][t] * s2 - T[2][t] * s1;
            const float cy = T[2][t] * s0 - T[0][t] * s2;
            const float cz = T[0][t] * s1 - T[1][t] * s0;
            o1[t * 3 + 0] = fmaf(BV[t], s0, A1[0][t]) + cx;
            o1[t * 3 + 1] = fmaf(BV[t], s1, A1[1][t]) + cy;
            o1[t * 3 + 2] = fmaf(BV[t], s2, A1[2][t]) + cz;
        }

        float* op = out + q * 64;
        *(float4*)(op + d0) = make_float4(o0[0], o0[1], o0[2], o0[3]);
        const int ob = 16 + 3 * d0;
        *(float4*)(op + ob + 0) = make_float4(o1[0], o1[1], o1[2],  o1[3]);
        *(float4*)(op + ob + 4) = make_float4(o1[4], o1[5], o1[6],  o1[7]);
        *(float4*)(op + ob + 8) = make_float4(o1[8], o1[9], o1[10], o1[11]);
    }
}

// ---------------------------------------------------------------------------
extern "C" void kernel_launch(void* const* d_in, const int* in_sizes, int n_in,
                              void* d_out, int out_size) {
    const float* feat = (const float*)d_in[0];
    const float* spin = (const float*)d_in[1];
    const float* w000 = (const float*)d_in[2];
    const float* w011 = (const float*)d_in[3];
    const float* w101 = (const float*)d_in[4];
    const float* w110 = (const float*)d_in[5];
    const float* w111 = (const float*)d_in[6];
    float* out = (float*)d_out;

    (void)in_sizes; (void)n_in; (void)out_size;

    cudaFuncSetAttribute(spinconv_kernel,
                         cudaFuncAttributeMaxDynamicSharedMemorySize, SMEM_BYTES);

    prep_weights<<<(NWFRAG + 255) / 256, 256>>>(w000, w011, w101, w110, w111);
    spinconv_kernel<<<8 * 128 * 2, 256, SMEM_BYTES>>>(feat, spin, out);
}

// round 11
// speedup vs baseline: 3.0117x; 1.3463x over previous
#include <cuda_runtime.h>
#include <cuda_fp16.h>
#include <cstdint>

// ---------------------------------------------------------------------------
// SpinConvSq2dSparse: N=8, Lx=Ly=128, C=16, K=9 (-> 5 effective taps), F_IN=64
// Round 11: f16 m16n8k16 MMA with register-resident epilogue.
//   Warp w: pixel block pb=w>>1 (16 px), nt parity par=w&1 (nt=par,par+2,par+4)
//   computes ALL 4 g-groups for its rows -> epilogue triplets (d,16+d,32+d)
//   and all g values live in the same lane; no stash / no epilogue smem.
//   Tile de-interleave in chunks of 6 (2 channels x 3 planes): no mod-3 math.
// ---------------------------------------------------------------------------

#define TPH  72      // f16 per tile pixel row (144B; ldmatrix conflict-free)
#define NTP  194     // tile pixels: 66 (center+y halo) + 64 (x-1) + 64 (x+1)
#define NWFRAG 3840  // 2 arrays x 5 taps x 6 nt x 2 regs x 32 lanes (u32)
#define TILE_HALFS (NTP * TPH)                  // 13968 halves = 6984 floats
#define SMEM_BYTES (NWFRAG * 4 + TILE_HALFS * 2)  // 15360 + 27936 = 43296 B

__device__ uint32_t g_Bfrag[NWFRAG];

// ---- mma helpers (sm_100a) ----
__device__ __forceinline__ void ldsm_x4(uint32_t* r, uint32_t addr) {
    asm volatile("ldmatrix.sync.aligned.m8n8.x4.shared.b16 {%0,%1,%2,%3}, [%4];"
                 : "=r"(r[0]), "=r"(r[1]), "=r"(r[2]), "=r"(r[3]) : "r"(addr));
}
__device__ __forceinline__ void mma_f16(float* c, const uint32_t* a, const uint32_t* b) {
    asm volatile("mma.sync.aligned.m16n8k16.row.col.f32.f16.f16.f32 "
                 "{%0,%1,%2,%3}, {%4,%5,%6,%7}, {%8,%9}, {%0,%1,%2,%3};"
                 : "+f"(c[0]), "+f"(c[1]), "+f"(c[2]), "+f"(c[3])
                 : "r"(a[0]), "r"(a[1]), "r"(a[2]), "r"(a[3]),
                   "r"(b[0]), "r"(b[1]));
}

// ---------------------------------------------------------------------------
// Effective weight (prefactors folded). tap0 = sum k=0..4 (center);
// tap1..4 = k=5..8 -> (x-1),(x+1),(y-1),(y+1).
// cols n: [0:16)=s110/a0-class, [16:32)=s101/b-class, [32:48)=t-class
// ---------------------------------------------------------------------------
__device__ __forceinline__ float effw(int isB, int tap, int c, int n,
                                      const float* w000, const float* w011,
                                      const float* w101, const float* w110,
                                      const float* w111) {
    const double C0  = 0.28209479177387814;
    const double C1  = 0.4886025119029199;
    const double IS3 = 0.57735026918962576;
    const double IS6 = 0.40824829046386302;
    const double PW0 = 0.058925565098878960;   // sqrt(1/(9*2*16))
    const double PW1 = 1.0 / 12.0;             // sqrt(3/(9*3*16))
    int cls = n >> 4, d = n & 15;
    int off = c * 16 + d;
    const float* w;
    double pf;
    if (!isB) {
        if (cls == 0)      { w = w110; pf = PW0 * IS3 * C1; }
        else if (cls == 1) { w = w101; pf = PW1 * C0 * IS3; }
        else               { w = w111; pf = PW1 * IS6 * C1; }
    } else {
        if (cls == 0)      { w = w000; pf = PW0 * C0; }
        else if (cls == 1) { w = w011; pf = PW1 * IS3 * C1; }
        else               return 0.f;
    }
    float s;
    if (tap == 0) {
        s = 0.f;
        #pragma unroll
        for (int k = 0; k < 5; k++) s += w[k * 256 + off];
    } else {
        s = w[(tap + 4) * 256 + off];
    }
    return (float)(pf * (double)s);
}

// Prep: emit B fragments in HMMA per-lane layout, packed f16x2.
// idx = arr*1920 + tap*384 + nt*64 + r*32 + lane
__global__ void prep_weights(const float* __restrict__ w000,
                             const float* __restrict__ w011,
                             const float* __restrict__ w101,
                             const float* __restrict__ w110,
                             const float* __restrict__ w111) {
    int idx = blockIdx.x * blockDim.x + threadIdx.x;
    if (idx >= NWFRAG) return;
    int l   = idx & 31;
    int r   = (idx >> 5) & 1;
    int nt  = (idx >> 6) % 6;
    int tap = ((idx >> 6) / 6) % 5;
    int arr = idx / 1920;
    int n  = 8 * nt + (l >> 2);
    int c0 = 2 * (l & 3) + 8 * r;
    float v0 = effw(arr, tap, c0,     n, w000, w011, w101, w110, w111);
    float v1 = effw(arr, tap, c0 + 1, n, w000, w011, w101, w110, w111);
    __half2 h = __floats2half2_rn(v0, v1);
    g_Bfrag[idx] = *(uint32_t*)&h;
}

// ---------------------------------------------------------------------------
// Main kernel: one CTA per (n, x, y-half of 64 pixels). 256 threads (8 warps).
// ---------------------------------------------------------------------------
__global__ __launch_bounds__(256, 3)
void spinconv_kernel(const float* __restrict__ feat,
                     const float* __restrict__ spin,
                     float* __restrict__ out) {
    extern __shared__ float smem[];
    uint32_t* sBw   = (uint32_t*)smem;          // 3840 u32 fragment words
    __half*   tileH = (__half*)(smem + NWFRAG); // f16 feat tile

    const int b   = blockIdx.x;
    const int n   = b >> 8;
    const int x   = (b >> 1) & 127;
    const int y0  = (b & 1) << 6;
    const int tid = threadIdx.x;

    // ---- copy pre-swizzled weight fragments to smem ----
    {
        const uint4* src = (const uint4*)g_Bfrag;
        uint4* dst = (uint4*)sBw;
        for (int i = tid; i < NWFRAG / 4; i += 256) dst[i] = src[i];
    }

    // ---- load feat tile, de-interleave to f16 planes:
    //      [x0(16) | x1_i0(16) | x1_i1(16) | x1_i2(16)] per pixel row.
    // 12 items/pixel: 4 x float4 (x0) + 8 chunks of 6 (x1: 2 ch x 3 planes) ----
    const int xm = (x + 127) & 127;
    const int xp = (x + 1) & 127;
    const size_t nbase = (size_t)n * (128 * 128 * 64);
    for (int idx = tid; idx < NTP * 12; idx += 256) {
        int tp = idx / 12;
        int s  = idx - tp * 12;
        int row, yy;
        if (tp < 66)       { row = x;  yy = (y0 + tp + 127) & 127; } // center + y halo
        else if (tp < 130) { row = xm; yy = y0 + (tp - 66); }        // x-1
        else               { row = xp; yy = y0 + (tp - 130); }       // x+1
        const float* src = feat + nbase + ((size_t)row * 128 + yy) * 64;
        __half* dst = tileH + tp * TPH;
        if (s < 4) {                       // x0 plane: 4 consecutive floats
            int f4 = s << 2;
            float4 v = *(const float4*)(src + f4);
            *(__half2*)(dst + f4)     = __floats2half2_rn(v.x, v.y);
            *(__half2*)(dst + f4 + 2) = __floats2half2_rn(v.z, v.w);
        } else {                           // x1: chunk j -> channels 2j,2j+1
            int j = s - 4;
            const float* u = src + 16 + 6 * j;
            float2 a = *(const float2*)(u);
            float2 c = *(const float2*)(u + 2);
            float2 e = *(const float2*)(u + 4);
            int c0 = 2 * j;
            *(__half2*)(dst + 16 + c0) = __floats2half2_rn(a.x, c.y); // i=0
            *(__half2*)(dst + 32 + c0) = __floats2half2_rn(a.y, e.x); // i=1
            *(__half2*)(dst + 48 + c0) = __floats2half2_rn(c.x, e.y); // i=2
        }
    }
    __syncthreads();

    // ---- tensor-core GEMM: warp w -> pixel block pb=w>>1, nt parity par=w&1.
    //      acc[g][ntl][4] with nt = par + 2*ntl; all 4 g for same rows. ----
    const int w    = tid >> 5;
    const int lane = tid & 31;
    const int pb   = w >> 1;                  // 0..3: pixels [16pb, 16pb+16)
    const int par  = w & 1;                   // nt parity
    const int laneRow = lane & 15;
    const int cOffB   = (lane & 16) ? 16 : 0; // k-half byte offset
    const uint32_t tbase = (uint32_t)__cvta_generic_to_shared(tileH);

    float acc[4][3][4];
    #pragma unroll
    for (int g = 0; g < 4; g++)
        #pragma unroll
        for (int t = 0; t < 3; t++)
            #pragma unroll
            for (int i = 0; i < 4; i++) acc[g][t][i] = 0.f;

    #pragma unroll
    for (int tap = 0; tap < 5; tap++) {
        // tile pixel of tap for pixel p: center=1+p, x-1=66+p, x+1=130+p, y-1=p, y+1=2+p
        const int tapbase = (tap == 0) ? 1 : (tap == 1) ? 66 : (tap == 2) ? 130 : (tap == 3) ? 0 : 2;
        const int rowb = (tapbase + (pb << 4) + laneRow) * (TPH * 2) + cOffB;

        // B fragments: set0 = WA (g=0..2 shared), set1 = WB (g=3)
        uint32_t B0[3][2], B1[3][2];
        const uint32_t* bp = sBw + tap * 384 + lane;
        #pragma unroll
        for (int t = 0; t < 3; t++) {
            const int nto = (par + 2 * t) * 64;
            B0[t][0] = bp[nto];          B0[t][1] = bp[nto + 32];
            B1[t][0] = bp[1920 + nto];   B1[t][1] = bp[1920 + nto + 32];
        }
        #pragma unroll
        for (int g = 0; g < 4; g++) {
            const int fb2 = (g == 3) ? 0 : ((1 + g) << 5);   // plane byte offset
            uint32_t a[4];
            ldsm_x4(a, tbase + (uint32_t)(rowb + fb2));
            #pragma unroll
            for (int t = 0; t < 3; t++)
                mma_f16(acc[g][t], a, (g == 3) ? B1[t] : B0[t]);
        }
    }

    // ---- register epilogue: lane owns rows lane/4 and lane/4+8 of the block,
    //      d values 8*par + 2*(lane&3) + {0,1}. ----
    const int m = lane & 3;
    #pragma unroll
    for (int sel = 0; sel < 2; sel++) {
        const int r = (lane >> 2) + 8 * sel;
        const int p = (pb << 4) + r;
        const size_t q = ((size_t)n * 128 + x) * 128 + (y0 + p);
        const float s0 = spin[q * 3 + 1];
        const float s1 = spin[q * 3 + 2];
        const float s2 = spin[q * 3 + 0];

        float o0[2], o1[2][3];
        #pragma unroll
        for (int e = 0; e < 2; e++) {
            const int i = 2 * sel + e;
            const float a0 = acc[3][0][i];
            const float bv = acc[3][1][i];
            const float h0 = acc[0][0][i], h1 = acc[1][0][i], h2 = acc[2][0][i];
            const float a10 = acc[0][1][i], a11 = acc[1][1][i], a12 = acc[2][1][i];
            const float t0 = acc[0][2][i], t1 = acc[1][2][i], t2 = acc[2][2][i];
            o0[e] = a0 + h0 * s0 + h1 * s1 + h2 * s2;
            o1[e][0] = fmaf(bv, s0, a10) + (t1 * s2 - t2 * s1);
            o1[e][1] = fmaf(bv, s1, a11) + (t2 * s0 - t0 * s2);
            o1[e][2] = fmaf(bv, s2, a12) + (t0 * s1 - t1 * s0);
        }
        float* op = out + q * 64;
        *(float2*)(op + 8 * par + 2 * m) = make_float2(o0[0], o0[1]);
        float* o1p = op + 16 + 24 * par + 6 * m;
        *(float2*)(o1p + 0) = make_float2(o1[0][0], o1[0][1]);
        *(float2*)(o1p + 2) = make_float2(o1[0][2], o1[1][0]);
        *(float2*)(o1p + 4) = make_float2(o1[1][1], o1[1][2]);
    }
}

// ---------------------------------------------------------------------------
extern "C" void kernel_launch(void* const* d_in, const int* in_sizes, int n_in,
                              void* d_out, int out_size) {
    const float* feat = (const float*)d_in[0];
    const float* spin = (const float*)d_in[1];
    const float* w000 = (const float*)d_in[2];
    const float* w011 = (const float*)d_in[3];
    const float* w101 = (const float*)d_in[4];
    const float* w110 = (const float*)d_in[5];
    const float* w111 = (const float*)d_in[6];
    float* out = (float*)d_out;

    (void)in_sizes; (void)n_in; (void)out_size;

    cudaFuncSetAttribute(spinconv_kernel,
                         cudaFuncAttributeMaxDynamicSharedMemorySize, SMEM_BYTES);

    prep_weights<<<(NWFRAG + 255) / 256, 256>>>(w000, w011, w101, w110, w111);
    spinconv_kernel<<<8 * 128 * 2, 256, SMEM_BYTES>>>(feat, spin, out);
}

// round 12
// speedup vs baseline: 3.5375x; 1.1746x over previous
#include <cuda_runtime.h>
#include <cuda_fp16.h>
#include <cstdint>

// ---------------------------------------------------------------------------
// SpinConvSq2dSparse: N=8, Lx=Ly=128, C=16, K=9 (-> 5 effective taps), F_IN=64
// Round 12: 2D output tile (4 x-rows x 16 y-cols) -> halo 108 px (was 194).
//   f16 m16n8k16 MMA, pre-swizzled B fragments, register-resident epilogue.
//   Tap shifts become tile-index offsets {0,-18,+18,-1,+1}.
//   De-interleave: x0 items of 8 floats (STS.128), x1 chunks of 12 floats
//   (4 channels x 3 planes, 3x STS.64, no mod-3 math).
// ---------------------------------------------------------------------------

#define TPH   72     // f16 per tile pixel row (144B; ldmatrix conflict-free)
#define NTP   108    // tile pixels: 6 rows x 18 cols
#define TROW  18     // tile pixels per x-row
#define NWFRAG 3840  // 2 arrays x 5 taps x 6 nt x 2 regs x 32 lanes (u32)
#define SMEM_BYTES (NWFRAG * 4 + NTP * TPH * 2)   // 15360 + 15552 = 30912 B

__device__ uint32_t g_Bfrag[NWFRAG];

// ---- mma helpers (sm_100a) ----
__device__ __forceinline__ void ldsm_x4(uint32_t* r, uint32_t addr) {
    asm volatile("ldmatrix.sync.aligned.m8n8.x4.shared.b16 {%0,%1,%2,%3}, [%4];"
                 : "=r"(r[0]), "=r"(r[1]), "=r"(r[2]), "=r"(r[3]) : "r"(addr));
}
__device__ __forceinline__ void mma_f16(float* c, const uint32_t* a, const uint32_t* b) {
    asm volatile("mma.sync.aligned.m16n8k16.row.col.f32.f16.f16.f32 "
                 "{%0,%1,%2,%3}, {%4,%5,%6,%7}, {%8,%9}, {%0,%1,%2,%3};"
                 : "+f"(c[0]), "+f"(c[1]), "+f"(c[2]), "+f"(c[3])
                 : "r"(a[0]), "r"(a[1]), "r"(a[2]), "r"(a[3]),
                   "r"(b[0]), "r"(b[1]));
}

// ---------------------------------------------------------------------------
// Effective weight (prefactors folded). tap0 = sum k=0..4 (center);
// tap1..4 = k=5..8 -> (x-1),(x+1),(y-1),(y+1).
// cols n: [0:16)=s110/a0-class, [16:32)=s101/b-class, [32:48)=t-class
// ---------------------------------------------------------------------------
__device__ __forceinline__ float effw(int isB, int tap, int c, int n,
                                      const float* w000, const float* w011,
                                      const float* w101, const float* w110,
                                      const float* w111) {
    const double C0  = 0.28209479177387814;
    const double C1  = 0.4886025119029199;
    const double IS3 = 0.57735026918962576;
    const double IS6 = 0.40824829046386302;
    const double PW0 = 0.058925565098878960;   // sqrt(1/(9*2*16))
    const double PW1 = 1.0 / 12.0;             // sqrt(3/(9*3*16))
    int cls = n >> 4, d = n & 15;
    int off = c * 16 + d;
    const float* w;
    double pf;
    if (!isB) {
        if (cls == 0)      { w = w110; pf = PW0 * IS3 * C1; }
        else if (cls == 1) { w = w101; pf = PW1 * C0 * IS3; }
        else               { w = w111; pf = PW1 * IS6 * C1; }
    } else {
        if (cls == 0)      { w = w000; pf = PW0 * C0; }
        else if (cls == 1) { w = w011; pf = PW1 * IS3 * C1; }
        else               return 0.f;
    }
    float s;
    if (tap == 0) {
        s = 0.f;
        #pragma unroll
        for (int k = 0; k < 5; k++) s += w[k * 256 + off];
    } else {
        s = w[(tap + 4) * 256 + off];
    }
    return (float)(pf * (double)s);
}

// Prep: emit B fragments in HMMA per-lane layout, packed f16x2.
// idx = arr*1920 + tap*384 + nt*64 + r*32 + lane
__global__ void prep_weights(const float* __restrict__ w000,
                             const float* __restrict__ w011,
                             const float* __restrict__ w101,
                             const float* __restrict__ w110,
                             const float* __restrict__ w111) {
    int idx = blockIdx.x * blockDim.x + threadIdx.x;
    if (idx >= NWFRAG) return;
    int l   = idx & 31;
    int r   = (idx >> 5) & 1;
    int nt  = (idx >> 6) % 6;
    int tap = ((idx >> 6) / 6) % 5;
    int arr = idx / 1920;
    int n  = 8 * nt + (l >> 2);
    int c0 = 2 * (l & 3) + 8 * r;
    float v0 = effw(arr, tap, c0,     n, w000, w011, w101, w110, w111);
    float v1 = effw(arr, tap, c0 + 1, n, w000, w011, w101, w110, w111);
    __half2 h = __floats2half2_rn(v0, v1);
    g_Bfrag[idx] = *(uint32_t*)&h;
}

// ---------------------------------------------------------------------------
// Main kernel: one CTA per (n, xb, yb): output tile 4 x-rows x 16 y-cols.
// 256 threads (8 warps). Warp w: m-tile (output row) pb=w>>1, nt parity w&1.
// ---------------------------------------------------------------------------
__global__ __launch_bounds__(256, 3)
void spinconv_kernel(const float* __restrict__ feat,
                     const float* __restrict__ spin,
                     float* __restrict__ out) {
    extern __shared__ float smem[];
    uint32_t* sBw   = (uint32_t*)smem;          // 3840 u32 fragment words
    __half*   tileH = (__half*)(smem + NWFRAG); // f16 feat tile

    const int b   = blockIdx.x;
    const int n   = b >> 8;
    const int xb  = (b >> 3) & 31;   // 32 blocks of 4 x-rows
    const int yb  = b & 7;           // 8 blocks of 16 y-cols
    const int tid = threadIdx.x;

    // ---- copy pre-swizzled weight fragments to smem ----
    {
        const uint4* src = (const uint4*)g_Bfrag;
        uint4* dst = (uint4*)sBw;
        for (int i = tid; i < NWFRAG / 4; i += 256) dst[i] = src[i];
    }

    // ---- load feat tile (108 px = 6 rows x 18 cols, circular halo),
    //      de-interleave to f16 planes [x0 | x1_i0 | x1_i1 | x1_i2].
    //      6 items/px: s<2 -> x0 8-float item (STS.128);
    //                  s>=2 -> x1 chunk of 12 floats (3x STS.64). ----
    const size_t nbase = (size_t)n * (128 * 128 * 64);
    for (int idx = tid; idx < NTP * 6; idx += 256) {
        int tp = idx / 6;
        int s  = idx - tp * 6;
        int tr = tp / TROW;
        int tc = tp - tr * TROW;
        int gx = (xb * 4 + tr + 127) & 127;
        int gy = (yb * 16 + tc + 127) & 127;
        const float* src = feat + nbase + ((size_t)gx * 128 + gy) * 64;
        __half* dst = tileH + tp * TPH;
        if (s < 2) {
            const float* u = src + 8 * s;
            float4 v0 = *(const float4*)(u);
            float4 v1 = *(const float4*)(u + 4);
            __half2 h0 = __floats2half2_rn(v0.x, v0.y);
            __half2 h1 = __floats2half2_rn(v0.z, v0.w);
            __half2 h2 = __floats2half2_rn(v1.x, v1.y);
            __half2 h3 = __floats2half2_rn(v1.z, v1.w);
            uint4 pk = make_uint4(*(uint32_t*)&h0, *(uint32_t*)&h1,
                                  *(uint32_t*)&h2, *(uint32_t*)&h3);
            *(uint4*)(dst + 8 * s) = pk;
        } else {
            int j = s - 2;                      // chunk: channels 4j..4j+3
            const float* u = src + 16 + 12 * j;
            float4 A = *(const float4*)(u);
            float4 B = *(const float4*)(u + 4);
            float4 C = *(const float4*)(u + 8);
            float f[12] = {A.x, A.y, A.z, A.w, B.x, B.y, B.z, B.w,
                           C.x, C.y, C.z, C.w};
            #pragma unroll
            for (int i = 0; i < 3; i++) {       // plane i
                __half2 lo = __floats2half2_rn(f[i],     f[3 + i]);
                __half2 hi = __floats2half2_rn(f[6 + i], f[9 + i]);
                uint2 pk;
                pk.x = *(uint32_t*)&lo;
                pk.y = *(uint32_t*)&hi;
                *(uint2*)(dst + (1 + i) * 16 + 4 * j) = pk;
            }
        }
    }
    __syncthreads();

    // ---- tensor-core GEMM: acc[g][t][4], nt = par + 2t, all 4 g same rows ----
    const int w    = tid >> 5;
    const int lane = tid & 31;
    const int pb   = w >> 1;                  // output row 0..3 (m-tile)
    const int par  = w & 1;                   // nt parity
    const int laneRow = lane & 15;
    const int cOffB   = (lane & 16) ? 16 : 0; // k-half byte offset
    const uint32_t tbase = (uint32_t)__cvta_generic_to_shared(tileH);
    const int rowc = (pb + 1) * TROW + 1 + laneRow;   // center tile pos

    float acc[4][3][4];
    #pragma unroll
    for (int g = 0; g < 4; g++)
        #pragma unroll
        for (int t = 0; t < 3; t++)
            #pragma unroll
            for (int i = 0; i < 4; i++) acc[g][t][i] = 0.f;

    const int tapoff[5] = {0, -TROW, TROW, -1, 1};   // center, x-1, x+1, y-1, y+1
    #pragma unroll
    for (int tap = 0; tap < 5; tap++) {
        const int rowb = (rowc + tapoff[tap]) * (TPH * 2) + cOffB;
        uint32_t B0[3][2], B1[3][2];
        const uint32_t* bp = sBw + tap * 384 + lane;
        #pragma unroll
        for (int t = 0; t < 3; t++) {
            const int nto = (par + 2 * t) * 64;
            B0[t][0] = bp[nto];          B0[t][1] = bp[nto + 32];
            B1[t][0] = bp[1920 + nto];   B1[t][1] = bp[1920 + nto + 32];
        }
        #pragma unroll
        for (int g = 0; g < 4; g++) {
            const int fb2 = (g == 3) ? 0 : ((1 + g) << 5);   // plane byte offset
            uint32_t a[4];
            ldsm_x4(a, tbase + (uint32_t)(rowb + fb2));
            #pragma unroll
            for (int t = 0; t < 3; t++)
                mma_f16(acc[g][t], a, (g == 3) ? B1[t] : B0[t]);
        }
    }

    // ---- register epilogue: lane owns cols c=(lane>>2)+8sel of row pb,
    //      d values 8*par + 2*(lane&3) + {0,1}. ----
    const int m  = lane & 3;
    const int gx = xb * 4 + pb;
    #pragma unroll
    for (int sel = 0; sel < 2; sel++) {
        const int c = (lane >> 2) + 8 * sel;
        const int gy = yb * 16 + c;
        const size_t q = ((size_t)n * 128 + gx) * 128 + gy;
        const float s0 = spin[q * 3 + 1];
        const float s1 = spin[q * 3 + 2];
        const float s2 = spin[q * 3 + 0];

        float o0[2], o1[2][3];
        #pragma unroll
        for (int e = 0; e < 2; e++) {
            const int i = 2 * sel + e;
            const float a0 = acc[3][0][i];
            const float bv = acc[3][1][i];
            const float h0 = acc[0][0][i], h1 = acc[1][0][i], h2 = acc[2][0][i];
            const float a10 = acc[0][1][i], a11 = acc[1][1][i], a12 = acc[2][1][i];
            const float t0 = acc[0][2][i], t1 = acc[1][2][i], t2 = acc[2][2][i];
            o0[e] = a0 + h0 * s0 + h1 * s1 + h2 * s2;
            o1[e][0] = fmaf(bv, s0, a10) + (t1 * s2 - t2 * s1);
            o1[e][1] = fmaf(bv, s1, a11) + (t2 * s0 - t0 * s2);
            o1[e][2] = fmaf(bv, s2, a12) + (t0 * s1 - t1 * s0);
        }
        float* op = out + q * 64;
        *(float2*)(op + 8 * par + 2 * m) = make_float2(o0[0], o0[1]);
        float* o1p = op + 16 + 24 * par + 6 * m;
        *(float2*)(o1p + 0) = make_float2(o1[0][0], o1[0][1]);
        *(float2*)(o1p + 2) = make_float2(o1[0][2], o1[1][0]);
        *(float2*)(o1p + 4) = make_float2(o1[1][1], o1[1][2]);
    }
}

// ---------------------------------------------------------------------------
extern "C" void kernel_launch(void* const* d_in, const int* in_sizes, int n_in,
                              void* d_out, int out_size) {
    const float* feat = (const float*)d_in[0];
    const float* spin = (const float*)d_in[1];
    const float* w000 = (const float*)d_in[2];
    const float* w011 = (const float*)d_in[3];
    const float* w101 = (const float*)d_in[4];
    const float* w110 = (const float*)d_in[5];
    const float* w111 = (const float*)d_in[6];
    float* out = (float*)d_out;

    (void)in_sizes; (void)n_in; (void)out_size;

    cudaFuncSetAttribute(spinconv_kernel,
                         cudaFuncAttributeMaxDynamicSharedMemorySize, SMEM_BYTES);

    prep_weights<<<(NWFRAG + 255) / 256, 256>>>(w000, w011, w101, w110, w111);
    spinconv_kernel<<<8 * 32 * 8, 256, SMEM_BYTES>>>(feat, spin, out);
}

// round 13
// speedup vs baseline: 3.5537x; 1.0046x over previous
#include <cuda_runtime.h>
#include <cuda_fp16.h>
#include <cstdint>

// ---------------------------------------------------------------------------
// SpinConvSq2dSparse: N=8, Lx=Ly=128, C=16, K=9 (-> 5 effective taps), F_IN=64
// Round 13: R12 (2D tile 4x16, f16 MMA, register epilogue) plus:
//   - dead g=3/t=2 work dropped (WB t-class cols are zero; acc[3][2] unused)
//   - B fragments read directly from global g_Bfrag (15KB, L1-resident) --
//     the per-CTA smem staging copy is deleted
//   - spin staged to smem coalesced; epilogue reads via broadcast LDS
// ---------------------------------------------------------------------------

#define TPH   72     // f16 per tile pixel row (144B; ldmatrix conflict-free)
#define NTP   108    // tile pixels: 6 rows x 18 cols
#define TROW  18     // tile pixels per x-row
#define NWFRAG 3840  // 2 arrays x 5 taps x 6 nt x 2 regs x 32 lanes (u32)
#define SMEM_BYTES (NTP * TPH * 2 + 192 * 4)   // tile 15552 + spin 768 = 16320 B

__device__ uint32_t g_Bfrag[NWFRAG];

// ---- mma helpers (sm_100a) ----
__device__ __forceinline__ void ldsm_x4(uint32_t* r, uint32_t addr) {
    asm volatile("ldmatrix.sync.aligned.m8n8.x4.shared.b16 {%0,%1,%2,%3}, [%4];"
                 : "=r"(r[0]), "=r"(r[1]), "=r"(r[2]), "=r"(r[3]) : "r"(addr));
}
__device__ __forceinline__ void mma_f16(float* c, const uint32_t* a, const uint32_t* b) {
    asm volatile("mma.sync.aligned.m16n8k16.row.col.f32.f16.f16.f32 "
                 "{%0,%1,%2,%3}, {%4,%5,%6,%7}, {%8,%9}, {%0,%1,%2,%3};"
                 : "+f"(c[0]), "+f"(c[1]), "+f"(c[2]), "+f"(c[3])
                 : "r"(a[0]), "r"(a[1]), "r"(a[2]), "r"(a[3]),
                   "r"(b[0]), "r"(b[1]));
}

// ---------------------------------------------------------------------------
// Effective weight (prefactors folded). tap0 = sum k=0..4 (center);
// tap1..4 = k=5..8 -> (x-1),(x+1),(y-1),(y+1).
// cols n: [0:16)=s110/a0-class, [16:32)=s101/b-class, [32:48)=t-class
// ---------------------------------------------------------------------------
__device__ __forceinline__ float effw(int isB, int tap, int c, int n,
                                      const float* w000, const float* w011,
                                      const float* w101, const float* w110,
                                      const float* w111) {
    const double C0  = 0.28209479177387814;
    const double C1  = 0.4886025119029199;
    const double IS3 = 0.57735026918962576;
    const double IS6 = 0.40824829046386302;
    const double PW0 = 0.058925565098878960;   // sqrt(1/(9*2*16))
    const double PW1 = 1.0 / 12.0;             // sqrt(3/(9*3*16))
    int cls = n >> 4, d = n & 15;
    int off = c * 16 + d;
    const float* w;
    double pf;
    if (!isB) {
        if (cls == 0)      { w = w110; pf = PW0 * IS3 * C1; }
        else if (cls == 1) { w = w101; pf = PW1 * C0 * IS3; }
        else               { w = w111; pf = PW1 * IS6 * C1; }
    } else {
        if (cls == 0)      { w = w000; pf = PW0 * C0; }
        else if (cls == 1) { w = w011; pf = PW1 * IS3 * C1; }
        else               return 0.f;
    }
    float s;
    if (tap == 0) {
        s = 0.f;
        #pragma unroll
        for (int k = 0; k < 5; k++) s += w[k * 256 + off];
    } else {
        s = w[(tap + 4) * 256 + off];
    }
    return (float)(pf * (double)s);
}

// Prep: emit B fragments in HMMA per-lane layout, packed f16x2.
// idx = arr*1920 + tap*384 + nt*64 + r*32 + lane
__global__ void prep_weights(const float* __restrict__ w000,
                             const float* __restrict__ w011,
                             const float* __restrict__ w101,
                             const float* __restrict__ w110,
                             const float* __restrict__ w111) {
    int idx = blockIdx.x * blockDim.x + threadIdx.x;
    if (idx >= NWFRAG) return;
    int l   = idx & 31;
    int r   = (idx >> 5) & 1;
    int nt  = (idx >> 6) % 6;
    int tap = ((idx >> 6) / 6) % 5;
    int arr = idx / 1920;
    int n  = 8 * nt + (l >> 2);
    int c0 = 2 * (l & 3) + 8 * r;
    float v0 = effw(arr, tap, c0,     n, w000, w011, w101, w110, w111);
    float v1 = effw(arr, tap, c0 + 1, n, w000, w011, w101, w110, w111);
    __half2 h = __floats2half2_rn(v0, v1);
    g_Bfrag[idx] = *(uint32_t*)&h;
}

// ---------------------------------------------------------------------------
// Main kernel: one CTA per (n, xb, yb): output tile 4 x-rows x 16 y-cols.
// 256 threads (8 warps). Warp w: m-tile (output row) pb=w>>1, nt parity w&1.
// ---------------------------------------------------------------------------
__global__ __launch_bounds__(256, 3)
void spinconv_kernel(const float* __restrict__ feat,
                     const float* __restrict__ spin,
                     float* __restrict__ out) {
    extern __shared__ float smem[];
    __half* tileH = (__half*)smem;              // f16 feat tile
    float*  sSpin = smem + (NTP * TPH) / 2;     // 192 floats (4 rows x 48)

    const int b   = blockIdx.x;
    const int n   = b >> 8;
    const int xb  = (b >> 3) & 31;   // 32 blocks of 4 x-rows
    const int yb  = b & 7;           // 8 blocks of 16 y-cols
    const int tid = threadIdx.x;

    // ---- stage spin block (4 x 16 px x 3) coalesced ----
    if (tid < 48) {
        int r = tid / 12, i = tid - r * 12;
        size_t q0 = ((size_t)n * 128 + xb * 4 + r) * 128 + yb * 16;
        float4 v = *(const float4*)(spin + q0 * 3 + i * 4);
        *(float4*)(sSpin + r * 48 + i * 4) = v;
    }

    // ---- load feat tile (108 px = 6 rows x 18 cols, circular halo),
    //      de-interleave to f16 planes [x0 | x1_i0 | x1_i1 | x1_i2]. ----
    const size_t nbase = (size_t)n * (128 * 128 * 64);
    for (int idx = tid; idx < NTP * 6; idx += 256) {
        int tp = idx / 6;
        int s  = idx - tp * 6;
        int tr = tp / TROW;
        int tc = tp - tr * TROW;
        int gx = (xb * 4 + tr + 127) & 127;
        int gy = (yb * 16 + tc + 127) & 127;
        const float* src = feat + nbase + ((size_t)gx * 128 + gy) * 64;
        __half* dst = tileH + tp * TPH;
        if (s < 2) {                           // x0 plane: 8 floats -> STS.128
            const float* u = src + 8 * s;
            float4 v0 = *(const float4*)(u);
            float4 v1 = *(const float4*)(u + 4);
            __half2 h0 = __floats2half2_rn(v0.x, v0.y);
            __half2 h1 = __floats2half2_rn(v0.z, v0.w);
            __half2 h2 = __floats2half2_rn(v1.x, v1.y);
            __half2 h3 = __floats2half2_rn(v1.z, v1.w);
            uint4 pk = make_uint4(*(uint32_t*)&h0, *(uint32_t*)&h1,
                                  *(uint32_t*)&h2, *(uint32_t*)&h3);
            *(uint4*)(dst + 8 * s) = pk;
        } else {                               // x1 chunk: channels 4j..4j+3
            int j = s - 2;
            const float* u = src + 16 + 12 * j;
            float4 A = *(const float4*)(u);
            float4 B = *(const float4*)(u + 4);
            float4 C = *(const float4*)(u + 8);
            float f[12] = {A.x, A.y, A.z, A.w, B.x, B.y, B.z, B.w,
                           C.x, C.y, C.z, C.w};
            #pragma unroll
            for (int i = 0; i < 3; i++) {      // plane i
                __half2 lo = __floats2half2_rn(f[i],     f[3 + i]);
                __half2 hi = __floats2half2_rn(f[6 + i], f[9 + i]);
                uint2 pk;
                pk.x = *(uint32_t*)&lo;
                pk.y = *(uint32_t*)&hi;
                *(uint2*)(dst + (1 + i) * 16 + 4 * j) = pk;
            }
        }
    }
    __syncthreads();

    // ---- tensor-core GEMM: acc[g][t][4], nt = par + 2t, all 4 g same rows.
    //      B fragments direct from global (L1-resident after first touch). ----
    const int w    = tid >> 5;
    const int lane = tid & 31;
    const int pb   = w >> 1;                  // output row 0..3 (m-tile)
    const int par  = w & 1;                   // nt parity
    const int laneRow = lane & 15;
    const int cOffB   = (lane & 16) ? 16 : 0; // k-half byte offset
    const uint32_t tbase = (uint32_t)__cvta_generic_to_shared(tileH);
    const int rowc = (pb + 1) * TROW + 1 + laneRow;   // center tile pos

    float acc[4][3][4];
    #pragma unroll
    for (int g = 0; g < 4; g++)
        #pragma unroll
        for (int t = 0; t < 3; t++)
            #pragma unroll
            for (int i = 0; i < 4; i++) acc[g][t][i] = 0.f;

    const int tapoff[5] = {0, -TROW, TROW, -1, 1};   // center, x-1, x+1, y-1, y+1
    #pragma unroll
    for (int tap = 0; tap < 5; tap++) {
        const int rowb = (rowc + tapoff[tap]) * (TPH * 2) + cOffB;
        // B fragments from global: WA all 3 nt, WB only nt par, par+2
        const uint32_t* bp = g_Bfrag + tap * 384 + lane;
        uint32_t B0[3][2], B1[2][2];
        #pragma unroll
        for (int t = 0; t < 3; t++) {
            const int nto = (par + 2 * t) * 64;
            B0[t][0] = __ldg(bp + nto);
            B0[t][1] = __ldg(bp + nto + 32);
        }
        #pragma unroll
        for (int t = 0; t < 2; t++) {
            const int nto = (par + 2 * t) * 64;
            B1[t][0] = __ldg(bp + 1920 + nto);
            B1[t][1] = __ldg(bp + 1920 + nto + 32);
        }
        #pragma unroll
        for (int g = 0; g < 4; g++) {
            const int fb2 = (g == 3) ? 0 : ((1 + g) << 5);   // plane byte offset
            uint32_t a[4];
            ldsm_x4(a, tbase + (uint32_t)(rowb + fb2));
            if (g < 3) {
                #pragma unroll
                for (int t = 0; t < 3; t++) mma_f16(acc[g][t], a, B0[t]);
            } else {
                #pragma unroll
                for (int t = 0; t < 2; t++) mma_f16(acc[g][t], a, B1[t]);
            }
        }
    }

    // ---- register epilogue: lane owns cols c=(lane>>2)+8sel of row pb,
    //      d values 8*par + 2*(lane&3) + {0,1}. ----
    const int m  = lane & 3;
    const int gx = xb * 4 + pb;
    #pragma unroll
    for (int sel = 0; sel < 2; sel++) {
        const int c = (lane >> 2) + 8 * sel;
        const int gy = yb * 16 + c;
        const size_t q = ((size_t)n * 128 + gx) * 128 + gy;
        const float* sp = sSpin + pb * 48 + c * 3;
        const float s0 = sp[1];
        const float s1 = sp[2];
        const float s2 = sp[0];

        float o0[2], o1[2][3];
        #pragma unroll
        for (int e = 0; e < 2; e++) {
            const int i = 2 * sel + e;
            const float a0 = acc[3][0][i];
            const float bv = acc[3][1][i];
            const float h0 = acc[0][0][i], h1 = acc[1][0][i], h2 = acc[2][0][i];
            const float a10 = acc[0][1][i], a11 = acc[1][1][i], a12 = acc[2][1][i];
            const float t0 = acc[0][2][i], t1 = acc[1][2][i], t2 = acc[2][2][i];
            o0[e] = a0 + h0 * s0 + h1 * s1 + h2 * s2;
            o1[e][0] = fmaf(bv, s0, a10) + (t1 * s2 - t2 * s1);
            o1[e][1] = fmaf(bv, s1, a11) + (t2 * s0 - t0 * s2);
            o1[e][2] = fmaf(bv, s2, a12) + (t0 * s1 - t1 * s0);
        }
        float* op = out + q * 64;
        *(float2*)(op + 8 * par + 2 * m) = make_float2(o0[0], o0[1]);
        float* o1p = op + 16 + 24 * par + 6 * m;
        *(float2*)(o1p + 0) = make_float2(o1[0][0], o1[0][1]);
        *(float2*)(o1p + 2) = make_float2(o1[0][2], o1[1][0]);
        *(float2*)(o1p + 4) = make_float2(o1[1][1], o1[1][2]);
    }
}

// ---------------------------------------------------------------------------
extern "C" void kernel_launch(void* const* d_in, const int* in_sizes, int n_in,
                              void* d_out, int out_size) {
    const float* feat = (const float*)d_in[0];
    const float* spin = (const float*)d_in[1];
    const float* w000 = (const float*)d_in[2];
    const float* w011 = (const float*)d_in[3];
    const float* w101 = (const float*)d_in[4];
    const float* w110 = (const float*)d_in[5];
    const float* w111 = (const float*)d_in[6];
    float* out = (float*)d_out;

    (void)in_sizes; (void)n_in; (void)out_size;

    cudaFuncSetAttribute(spinconv_kernel,
                         cudaFuncAttributeMaxDynamicSharedMemorySize, SMEM_BYTES);

    prep_weights<<<(NWFRAG + 255) / 256, 256>>>(w000, w011, w101, w110, w111);
    spinconv_kernel<<<8 * 32 * 8, 256, SMEM_BYTES>>>(feat, spin, out);
}